// round 2
// baseline (speedup 1.0000x reference)
#include <cuda_runtime.h>

// Problem constants (shape-specialized)
#define NN 50000       // nodes
#define NE 800000      // edges
#define IND 128        // input dim
#define FD  256        // HEADS*HID
#define HID 64
#define NG  64         // graphs
#define NC  10         // classes
#define SLOPE 0.2f

// ---------------- device scratch (no allocations allowed) ----------------
__device__ float   g_featA[NN * FD];   // projected features of current layer
__device__ float   g_featB[NN * FD];   // aggregated output / next-layer input
__device__ float   g_el[NN * 4];
__device__ float   g_er[NN * 4];
__device__ int     g_rowptr[NN + 1];
__device__ int     g_cnt[NN];
__device__ int     g_esrc[NE];         // src node id, sorted by dst (CSR)
__device__ unsigned g_pool[NG * HID];  // ordered-uint max-pool accumulator

// ---------------- helpers ----------------
__device__ __forceinline__ unsigned f2ord(float f) {
    unsigned u = __float_as_uint(f);
    return (u >> 31) ? ~u : (u | 0x80000000u);
}
__device__ __forceinline__ float ord2f(unsigned u) {
    return (u >> 31) ? __uint_as_float(u & 0x7fffffffu) : __uint_as_float(~u);
}
__device__ __forceinline__ float lrelu(float x) { return x > 0.f ? x : SLOPE * x; }

// ---------------- SGEMM: C[M,256] = A[M,K] @ B[K,256] ----------------
// BM=128, BN=128, BK=8, 256 threads, 8x8 per thread.
template <int K>
__global__ __launch_bounds__(256) void sgemm_kernel(const float* __restrict__ A,
                                                    const float* __restrict__ B,
                                                    float* __restrict__ C, int M)
{
    __shared__ float As[8][128];
    __shared__ float Bs[8][128];
    const int tid  = threadIdx.x;
    const int row0 = blockIdx.x * 128;
    const int col0 = blockIdx.y * 128;

    const int a_row = tid >> 1;           // 0..127
    const int a_col = (tid & 1) * 4;      // 0 or 4
    const int b_row = tid >> 5;           // 0..7
    const int b_col = (tid & 31) * 4;     // 0..124

    const int ty = tid >> 4;              // 0..15
    const int tx = tid & 15;              // 0..15

    float acc[8][8];
#pragma unroll
    for (int i = 0; i < 8; i++)
#pragma unroll
        for (int j = 0; j < 8; j++) acc[i][j] = 0.f;

    for (int k0 = 0; k0 < K; k0 += 8) {
        float4 av = make_float4(0.f, 0.f, 0.f, 0.f);
        int gr = row0 + a_row;
        if (gr < M) av = *reinterpret_cast<const float4*>(&A[(long)gr * K + k0 + a_col]);
        As[a_col + 0][a_row] = av.x;
        As[a_col + 1][a_row] = av.y;
        As[a_col + 2][a_row] = av.z;
        As[a_col + 3][a_row] = av.w;

        float4 bv = *reinterpret_cast<const float4*>(&B[(k0 + b_row) * FD + col0 + b_col]);
        *reinterpret_cast<float4*>(&Bs[b_row][b_col]) = bv;
        __syncthreads();

#pragma unroll
        for (int kk = 0; kk < 8; kk++) {
            float a[8], b[8];
            float4 a0 = *reinterpret_cast<const float4*>(&As[kk][ty * 8]);
            float4 a1 = *reinterpret_cast<const float4*>(&As[kk][ty * 8 + 4]);
            float4 b0 = *reinterpret_cast<const float4*>(&Bs[kk][tx * 8]);
            float4 b1 = *reinterpret_cast<const float4*>(&Bs[kk][tx * 8 + 4]);
            a[0]=a0.x; a[1]=a0.y; a[2]=a0.z; a[3]=a0.w; a[4]=a1.x; a[5]=a1.y; a[6]=a1.z; a[7]=a1.w;
            b[0]=b0.x; b[1]=b0.y; b[2]=b0.z; b[3]=b0.w; b[4]=b1.x; b[5]=b1.y; b[6]=b1.z; b[7]=b1.w;
#pragma unroll
            for (int i = 0; i < 8; i++)
#pragma unroll
                for (int j = 0; j < 8; j++) acc[i][j] = fmaf(a[i], b[j], acc[i][j]);
        }
        __syncthreads();
    }

#pragma unroll
    for (int i = 0; i < 8; i++) {
        int gr = row0 + ty * 8 + i;
        if (gr >= M) continue;
        float4 v0 = make_float4(acc[i][0], acc[i][1], acc[i][2], acc[i][3]);
        float4 v1 = make_float4(acc[i][4], acc[i][5], acc[i][6], acc[i][7]);
        *reinterpret_cast<float4*>(&C[(long)gr * FD + col0 + tx * 8])     = v0;
        *reinterpret_cast<float4*>(&C[(long)gr * FD + col0 + tx * 8 + 4]) = v1;
    }
}

// ---------------- attention coefficients: el/er per node ----------------
__global__ __launch_bounds__(256) void attn_kernel(const float* __restrict__ feat,
                                                   const float* __restrict__ al,
                                                   const float* __restrict__ ar)
{
    int warp = blockIdx.x * 8 + (threadIdx.x >> 5);
    int lane = threadIdx.x & 31;
    if (warp >= NN) return;
    const float* fr = &feat[(long)warp * FD];
    float sl[4] = {0.f, 0.f, 0.f, 0.f};
    float sr[4] = {0.f, 0.f, 0.f, 0.f};
#pragma unroll
    for (int k = 0; k < 8; k++) {
        int f = k * 32 + lane;
        float v = fr[f];
        sl[k >> 1] = fmaf(v, al[f], sl[k >> 1]);
        sr[k >> 1] = fmaf(v, ar[f], sr[k >> 1]);
    }
#pragma unroll
    for (int o = 16; o > 0; o >>= 1) {
#pragma unroll
        for (int h = 0; h < 4; h++) {
            sl[h] += __shfl_xor_sync(0xffffffffu, sl[h], o);
            sr[h] += __shfl_xor_sync(0xffffffffu, sr[h], o);
        }
    }
    if (lane == 0) {
        *reinterpret_cast<float4*>(&g_el[warp * 4]) = make_float4(sl[0], sl[1], sl[2], sl[3]);
        *reinterpret_cast<float4*>(&g_er[warp * 4]) = make_float4(sr[0], sr[1], sr[2], sr[3]);
    }
}

// ---------------- CSR build ----------------
__global__ void zero_cnt_kernel() {
    int i = blockIdx.x * blockDim.x + threadIdx.x;
    if (i < NN) g_cnt[i] = 0;
}
__global__ void count_deg_kernel(const int* __restrict__ ei) {
    int e = blockIdx.x * blockDim.x + threadIdx.x;
    if (e < NE) atomicAdd(&g_cnt[ei[NE + e]], 1);
}
__global__ __launch_bounds__(1024) void scan_kernel() {
    __shared__ int sh[1024];
    const int t = threadIdx.x;
    const int CH = 49;  // ceil(50000/1024)
    int b = t * CH;
    int e = min(b + CH, NN);
    int s = 0;
    for (int i = b; i < e; i++) s += g_cnt[i];
    sh[t] = s;
    __syncthreads();
    int own = s;
    for (int off = 1; off < 1024; off <<= 1) {
        int v = (t >= off) ? sh[t - off] : 0;
        __syncthreads();
        sh[t] += v;
        __syncthreads();
    }
    int run = sh[t] - own;  // exclusive prefix at chunk start
    for (int i = b; i < e; i++) {
        int c = g_cnt[i];
        g_rowptr[i] = run;
        run += c;
    }
    if (t == 1023) g_rowptr[NN] = sh[1023];
}
__global__ void scatter_kernel(const int* __restrict__ ei) {
    int e = blockIdx.x * blockDim.x + threadIdx.x;
    if (e < NE) {
        int s = ei[e];
        int d = ei[NE + e];
        int pos = g_rowptr[d] + atomicAdd(&g_cnt[d], 1);
        g_esrc[pos] = s;
    }
}

// ---------------- GAT edge softmax + aggregation: warp per dst node ----------------
__global__ __launch_bounds__(256) void gat_aggregate_kernel(const float* __restrict__ feat,
                                                            const float* __restrict__ bias,
                                                            float* __restrict__ out)
{
    int n    = blockIdx.x * 8 + (threadIdx.x >> 5);
    int lane = threadIdx.x & 31;
    if (n >= NN) return;
    int start = g_rowptr[n];
    int end   = g_rowptr[n + 1];

    float acc[8];
#pragma unroll
    for (int k = 0; k < 8; k++) acc[k] = 0.f;

    if (end > start) {
        float4 er4 = *reinterpret_cast<const float4*>(&g_er[n * 4]);
        // pass A: per-head max of leaky_relu(el[src] + er[dst])
        float m0 = -1e30f, m1 = -1e30f, m2 = -1e30f, m3 = -1e30f;
        for (int i = start + lane; i < end; i += 32) {
            int s = g_esrc[i];
            float4 el4 = *reinterpret_cast<const float4*>(&g_el[s * 4]);
            m0 = fmaxf(m0, lrelu(el4.x + er4.x));
            m1 = fmaxf(m1, lrelu(el4.y + er4.y));
            m2 = fmaxf(m2, lrelu(el4.z + er4.z));
            m3 = fmaxf(m3, lrelu(el4.w + er4.w));
        }
#pragma unroll
        for (int o = 16; o > 0; o >>= 1) {
            m0 = fmaxf(m0, __shfl_xor_sync(0xffffffffu, m0, o));
            m1 = fmaxf(m1, __shfl_xor_sync(0xffffffffu, m1, o));
            m2 = fmaxf(m2, __shfl_xor_sync(0xffffffffu, m2, o));
            m3 = fmaxf(m3, __shfl_xor_sync(0xffffffffu, m3, o));
        }
        // pass B: denom
        float d0 = 0.f, d1 = 0.f, d2 = 0.f, d3 = 0.f;
        for (int i = start + lane; i < end; i += 32) {
            int s = g_esrc[i];
            float4 el4 = *reinterpret_cast<const float4*>(&g_el[s * 4]);
            d0 += __expf(lrelu(el4.x + er4.x) - m0);
            d1 += __expf(lrelu(el4.y + er4.y) - m1);
            d2 += __expf(lrelu(el4.z + er4.z) - m2);
            d3 += __expf(lrelu(el4.w + er4.w) - m3);
        }
#pragma unroll
        for (int o = 16; o > 0; o >>= 1) {
            d0 += __shfl_xor_sync(0xffffffffu, d0, o);
            d1 += __shfl_xor_sync(0xffffffffu, d1, o);
            d2 += __shfl_xor_sync(0xffffffffu, d2, o);
            d3 += __shfl_xor_sync(0xffffffffu, d3, o);
        }
        float i0 = 1.f / fmaxf(d0, 1e-9f);
        float i1 = 1.f / fmaxf(d1, 1e-9f);
        float i2 = 1.f / fmaxf(d2, 1e-9f);
        float i3 = 1.f / fmaxf(d3, 1e-9f);
        // pass C: weighted gather-sum, software-pipelined 1 deep.
        int s_cur = g_esrc[start];
        float4 el_cur = *reinterpret_cast<const float4*>(&g_el[s_cur * 4]);
        for (int i = start; i < end; i++) {
            int s_nxt = 0;
            float4 el_nxt = el_cur;
            if (i + 1 < end) {
                s_nxt = g_esrc[i + 1];
                el_nxt = *reinterpret_cast<const float4*>(&g_el[s_nxt * 4]);
            }
            float a0 = __expf(lrelu(el_cur.x + er4.x) - m0) * i0;
            float a1 = __expf(lrelu(el_cur.y + er4.y) - m1) * i1;
            float a2 = __expf(lrelu(el_cur.z + er4.z) - m2) * i2;
            float a3 = __expf(lrelu(el_cur.w + er4.w) - m3) * i3;
            const float* fr = &feat[(long)s_cur * FD];
#pragma unroll
            for (int k = 0; k < 8; k++) {
                float a = (k < 2) ? a0 : (k < 4) ? a1 : (k < 6) ? a2 : a3;
                acc[k] = fmaf(a, fr[k * 32 + lane], acc[k]);
            }
            s_cur = s_nxt;
            el_cur = el_nxt;
        }
    }
#pragma unroll
    for (int k = 0; k < 8; k++) {
        int f = k * 32 + lane;
        float v = acc[k] + bias[f];
        out[(long)n * FD + f] = v > 0.f ? v : 0.f;
    }
}

// ---------------- pooling ----------------
__global__ void pool_init_kernel() {
    int i = blockIdx.x * blockDim.x + threadIdx.x;
    if (i < NG * HID) g_pool[i] = f2ord(-3.0e38f);
}
__global__ __launch_bounds__(256) void pool_kernel(const int* __restrict__ graph_ids) {
    int n    = blockIdx.x * 8 + (threadIdx.x >> 5);
    int lane = threadIdx.x & 31;
    if (n >= NN) return;
    int g = graph_ids[n];
    const float* x = &g_featB[(long)n * FD];
#pragma unroll
    for (int r = 0; r < 2; r++) {
        int d = lane + r * 32;
        float hm = 0.25f * (x[d] + x[64 + d] + x[128 + d] + x[192 + d]);
        atomicMax(&g_pool[g * HID + d], f2ord(hm));
    }
}
__global__ void classifier_kernel(const float* __restrict__ Wc,
                                  const float* __restrict__ bc,
                                  float* __restrict__ out)
{
    int t = blockIdx.x * blockDim.x + threadIdx.x;
    if (t >= NG * NC) return;
    int g = t / NC;
    int c = t % NC;
    float s = bc[c];
#pragma unroll 8
    for (int d = 0; d < HID; d++)
        s = fmaf(ord2f(g_pool[g * HID + d]), Wc[d * NC + c], s);
    out[t] = s;
}

// ---------------- host launcher ----------------
extern "C" void kernel_launch(void* const* d_in, const int* in_sizes, int n_in,
                              void* d_out, int out_size)
{
    const float* h   = (const float*)d_in[0];
    const float* W1  = (const float*)d_in[1];
    const float* al1 = (const float*)d_in[2];
    const float* ar1 = (const float*)d_in[3];
    const float* b1  = (const float*)d_in[4];
    const float* W2  = (const float*)d_in[5];
    const float* al2 = (const float*)d_in[6];
    const float* ar2 = (const float*)d_in[7];
    const float* b2  = (const float*)d_in[8];
    const float* Wc  = (const float*)d_in[9];
    const float* bc  = (const float*)d_in[10];
    const int* ei    = (const int*)d_in[11];
    const int* gid   = (const int*)d_in[12];
    float* out = (float*)d_out;

    void *pA = nullptr, *pB = nullptr;
    cudaGetSymbolAddress(&pA, g_featA);
    cudaGetSymbolAddress(&pB, g_featB);
    float* featA = (float*)pA;
    float* featB = (float*)pB;

    const int warp_blocks = (NN + 7) / 8;  // 8 warps per 256-thread block

    // CSR build (layer-independent)
    zero_cnt_kernel<<<(NN + 255) / 256, 256>>>();
    count_deg_kernel<<<(NE + 255) / 256, 256>>>(ei);
    scan_kernel<<<1, 1024>>>();
    zero_cnt_kernel<<<(NN + 255) / 256, 256>>>();
    scatter_kernel<<<(NE + 255) / 256, 256>>>(ei);

    // Layer 1
    {
        dim3 grid((NN + 127) / 128, FD / 128);
        sgemm_kernel<IND><<<grid, 256>>>(h, W1, featA, NN);
    }
    attn_kernel<<<warp_blocks, 256>>>(featA, al1, ar1);
    gat_aggregate_kernel<<<warp_blocks, 256>>>(featA, b1, featB);

    // Layer 2
    {
        dim3 grid((NN + 127) / 128, FD / 128);
        sgemm_kernel<FD><<<grid, 256>>>(featB, W2, featA, NN);
    }
    attn_kernel<<<warp_blocks, 256>>>(featA, al2, ar2);
    gat_aggregate_kernel<<<warp_blocks, 256>>>(featA, b2, featB);

    // Head-mean + per-graph max pool + classifier
    pool_init_kernel<<<(NG * HID + 255) / 256, 256>>>();
    pool_kernel<<<warp_blocks, 256>>>(gid);
    classifier_kernel<<<(NG * NC + 255) / 256, 256>>>(Wc, bc, out);
}

// round 3
// speedup vs baseline: 1.3957x; 1.3957x over previous
#include <cuda_runtime.h>

// Problem constants (shape-specialized)
#define NN 50000       // nodes
#define NE 800000      // edges
#define IND 128        // input dim
#define FD  256        // HEADS*HID
#define HID 64
#define NG  64         // graphs
#define NC  10         // classes
#define SLOPE 0.2f

// ---------------- device scratch (no allocations allowed) ----------------
__device__ float   g_featA[NN * FD];   // projected features of current layer
__device__ float   g_featB[NN * FD];   // aggregated output / next-layer input
__device__ float   g_el[NN * 4];
__device__ float   g_er[NN * 4];
__device__ int     g_rowptr[NN + 1];
__device__ int     g_cnt[NN];
__device__ int     g_esrc[NE];         // src node id, sorted by dst (CSR)
__device__ unsigned g_pool[NG * HID];  // ordered-uint max-pool accumulator

// ---------------- helpers ----------------
__device__ __forceinline__ unsigned f2ord(float f) {
    unsigned u = __float_as_uint(f);
    return (u >> 31) ? ~u : (u | 0x80000000u);
}
__device__ __forceinline__ float ord2f(unsigned u) {
    return (u >> 31) ? __uint_as_float(u & 0x7fffffffu) : __uint_as_float(~u);
}
__device__ __forceinline__ float lrelu(float x) { return x > 0.f ? x : SLOPE * x; }

__device__ __forceinline__ unsigned f2tf32(float x) {
    unsigned r;
    asm("cvt.rna.tf32.f32 %0, %1;" : "=r"(r) : "f"(x));
    return r;
}
__device__ __forceinline__ void mma_tf32(float c[4], const unsigned a[4], const unsigned b[2]) {
    asm volatile(
        "mma.sync.aligned.m16n8k8.row.col.f32.tf32.tf32.f32 "
        "{%0,%1,%2,%3}, {%4,%5,%6,%7}, {%8,%9}, {%0,%1,%2,%3};"
        : "+f"(c[0]), "+f"(c[1]), "+f"(c[2]), "+f"(c[3])
        : "r"(a[0]), "r"(a[1]), "r"(a[2]), "r"(a[3]), "r"(b[0]), "r"(b[1]));
}

// ---------------- fused tf32 GEMM + attention coefficients ----------------
// C[M,256] = A[M,K] @ B[K,256]  (tf32 inputs, fp32 accumulate)
// Epilogue also writes g_el[n][h] = sum_d C[n][h*64+d]*al[h*64+d], g_er likewise.
// Block tile 128x256 (full width), BK=16, 8 warps of 64x64. Warp-col == head.
template <int K>
__global__ __launch_bounds__(256) void gemm_attn_kernel(const float* __restrict__ A,
                                                        const float* __restrict__ B,
                                                        float* __restrict__ C,
                                                        const float* __restrict__ al,
                                                        const float* __restrict__ ar)
{
    __shared__ unsigned As[128 * 17];   // [m][k], stride 17 (16 + pad)
    __shared__ unsigned Bs[256 * 17];   // [n][k], stride 17

    const int tid  = threadIdx.x;
    const int lane = tid & 31;
    const int wid  = tid >> 5;
    const int wr   = wid >> 2;          // warp row 0..1 (64 rows each)
    const int wc   = wid & 3;           // warp col 0..3 (64 cols each = 1 head)
    const int lr   = lane >> 2;         // 0..7
    const int lq   = lane & 3;          // 0..3
    const int row0 = blockIdx.x * 128;

    float c[4][8][4];
#pragma unroll
    for (int mt = 0; mt < 4; mt++)
#pragma unroll
        for (int nt = 0; nt < 8; nt++)
#pragma unroll
            for (int i = 0; i < 4; i++) c[mt][nt][i] = 0.f;

    const int a_r = tid >> 2;           // 0..63
    const int a_c = (tid & 3) * 4;      // 0,4,8,12

    float4 apf[2];
    float4 bpf[4];

#define LD_TILE(k0)                                                                   \
    do {                                                                              \
        _Pragma("unroll")                                                             \
        for (int i = 0; i < 2; i++) {                                                 \
            int r = row0 + a_r + i * 64;                                              \
            apf[i] = (r < NN) ? *reinterpret_cast<const float4*>(&A[(long)r * K + (k0) + a_c]) \
                              : make_float4(0.f, 0.f, 0.f, 0.f);                      \
        }                                                                             \
        _Pragma("unroll")                                                             \
        for (int i = 0; i < 4; i++) {                                                 \
            int idx = tid + i * 256;                                                  \
            int br = idx >> 6, bc = (idx & 63) * 4;                                   \
            bpf[i] = *reinterpret_cast<const float4*>(&B[(long)((k0) + br) * FD + bc]); \
        }                                                                             \
    } while (0)

#define ST_TILE()                                                                     \
    do {                                                                              \
        _Pragma("unroll")                                                             \
        for (int i = 0; i < 2; i++) {                                                 \
            int m = a_r + i * 64;                                                     \
            As[m * 17 + a_c + 0] = f2tf32(apf[i].x);                                  \
            As[m * 17 + a_c + 1] = f2tf32(apf[i].y);                                  \
            As[m * 17 + a_c + 2] = f2tf32(apf[i].z);                                  \
            As[m * 17 + a_c + 3] = f2tf32(apf[i].w);                                  \
        }                                                                             \
        _Pragma("unroll")                                                             \
        for (int i = 0; i < 4; i++) {                                                 \
            int idx = tid + i * 256;                                                  \
            int br = idx >> 6, bc = (idx & 63) * 4;                                   \
            Bs[(bc + 0) * 17 + br] = f2tf32(bpf[i].x);                                \
            Bs[(bc + 1) * 17 + br] = f2tf32(bpf[i].y);                                \
            Bs[(bc + 2) * 17 + br] = f2tf32(bpf[i].z);                                \
            Bs[(bc + 3) * 17 + br] = f2tf32(bpf[i].w);                                \
        }                                                                             \
    } while (0)

    LD_TILE(0);
    ST_TILE();
    __syncthreads();

    const int NT = K / 16;
    for (int t = 0; t < NT; t++) {
        if (t + 1 < NT) LD_TILE((t + 1) * 16);

#pragma unroll
        for (int ks = 0; ks < 2; ks++) {
            const int k = ks * 8;
            unsigned af[4][4], bf[8][2];
#pragma unroll
            for (int mt = 0; mt < 4; mt++) {
                int m = wr * 64 + mt * 16 + lr;
                af[mt][0] = As[m * 17 + k + lq];
                af[mt][1] = As[(m + 8) * 17 + k + lq];
                af[mt][2] = As[m * 17 + k + lq + 4];
                af[mt][3] = As[(m + 8) * 17 + k + lq + 4];
            }
#pragma unroll
            for (int nt = 0; nt < 8; nt++) {
                int n = wc * 64 + nt * 8 + lr;
                bf[nt][0] = Bs[n * 17 + k + lq];
                bf[nt][1] = Bs[n * 17 + k + lq + 4];
            }
#pragma unroll
            for (int mt = 0; mt < 4; mt++)
#pragma unroll
                for (int nt = 0; nt < 8; nt++)
                    mma_tf32(c[mt][nt], af[mt], bf[nt]);
        }
        __syncthreads();
        if (t + 1 < NT) {
            ST_TILE();
            __syncthreads();
        }
    }
#undef LD_TILE
#undef ST_TILE

    // Epilogue: store C (float2 pairs) and accumulate per-row el/er partials.
    float elp[8], erp[8];
#pragma unroll
    for (int h = 0; h < 8; h++) { elp[h] = 0.f; erp[h] = 0.f; }

#pragma unroll
    for (int mt = 0; mt < 4; mt++) {
        int r0 = row0 + wr * 64 + mt * 16 + lr;
#pragma unroll
        for (int nt = 0; nt < 8; nt++) {
            int col = wc * 64 + nt * 8 + 2 * lq;
            float al0 = al[col], al1 = al[col + 1];
            float ar0 = ar[col], ar1 = ar[col + 1];
            float v0 = c[mt][nt][0], v1 = c[mt][nt][1];
            float v2 = c[mt][nt][2], v3 = c[mt][nt][3];
            if (r0 < NN)
                *reinterpret_cast<float2*>(&C[(long)r0 * FD + col]) = make_float2(v0, v1);
            if (r0 + 8 < NN)
                *reinterpret_cast<float2*>(&C[(long)(r0 + 8) * FD + col]) = make_float2(v2, v3);
            elp[mt * 2]     += v0 * al0 + v1 * al1;
            erp[mt * 2]     += v0 * ar0 + v1 * ar1;
            elp[mt * 2 + 1] += v2 * al0 + v3 * al1;
            erp[mt * 2 + 1] += v2 * ar0 + v3 * ar1;
        }
    }
#pragma unroll
    for (int h = 0; h < 8; h++) {
        elp[h] += __shfl_xor_sync(0xffffffffu, elp[h], 1);
        elp[h] += __shfl_xor_sync(0xffffffffu, elp[h], 2);
        erp[h] += __shfl_xor_sync(0xffffffffu, erp[h], 1);
        erp[h] += __shfl_xor_sync(0xffffffffu, erp[h], 2);
    }
    if (lq == 0) {
#pragma unroll
        for (int mt = 0; mt < 4; mt++) {
            int r0 = row0 + wr * 64 + mt * 16 + lr;
            if (r0 < NN)     { g_el[r0 * 4 + wc] = elp[mt * 2];     g_er[r0 * 4 + wc] = erp[mt * 2]; }
            if (r0 + 8 < NN) { g_el[(r0 + 8) * 4 + wc] = elp[mt * 2 + 1]; g_er[(r0 + 8) * 4 + wc] = erp[mt * 2 + 1]; }
        }
    }
}

// ---------------- CSR build ----------------
__global__ void zero_cnt_kernel() {
    int i = blockIdx.x * blockDim.x + threadIdx.x;
    if (i < NN) g_cnt[i] = 0;
}
__global__ void count_deg_kernel(const int* __restrict__ ei) {
    int e = blockIdx.x * blockDim.x + threadIdx.x;
    if (e < NE) atomicAdd(&g_cnt[ei[NE + e]], 1);
}
__global__ __launch_bounds__(1024) void scan_kernel() {
    __shared__ int sh[1024];
    const int t = threadIdx.x;
    const int CH = 49;  // ceil(50000/1024)
    int b = t * CH;
    int e = min(b + CH, NN);
    int s = 0;
    for (int i = b; i < e; i++) s += g_cnt[i];
    sh[t] = s;
    __syncthreads();
    int own = s;
    for (int off = 1; off < 1024; off <<= 1) {
        int v = (t >= off) ? sh[t - off] : 0;
        __syncthreads();
        sh[t] += v;
        __syncthreads();
    }
    int run = sh[t] - own;  // exclusive prefix at chunk start
    for (int i = b; i < e; i++) {
        int c = g_cnt[i];
        g_rowptr[i] = run;
        run += c;
    }
    if (t == 1023) g_rowptr[NN] = sh[1023];
}
__global__ void scatter_kernel(const int* __restrict__ ei) {
    int e = blockIdx.x * blockDim.x + threadIdx.x;
    if (e < NE) {
        int s = ei[e];
        int d = ei[NE + e];
        int pos = g_rowptr[d] + atomicAdd(&g_cnt[d], 1);
        g_esrc[pos] = s;
    }
}

// ---------------- GAT edge softmax + aggregation: warp per dst node ----------------
__global__ __launch_bounds__(256) void gat_aggregate_kernel(const float* __restrict__ feat,
                                                            const float* __restrict__ bias,
                                                            float* __restrict__ out)
{
    int n    = blockIdx.x * 8 + (threadIdx.x >> 5);
    int lane = threadIdx.x & 31;
    if (n >= NN) return;
    int start = g_rowptr[n];
    int end   = g_rowptr[n + 1];

    float acc[8];
#pragma unroll
    for (int k = 0; k < 8; k++) acc[k] = 0.f;

    if (end > start) {
        float4 er4 = *reinterpret_cast<const float4*>(&g_er[n * 4]);
        // pass A: per-head max of leaky_relu(el[src] + er[dst])
        float m0 = -1e30f, m1 = -1e30f, m2 = -1e30f, m3 = -1e30f;
        for (int i = start + lane; i < end; i += 32) {
            int s = g_esrc[i];
            float4 el4 = *reinterpret_cast<const float4*>(&g_el[s * 4]);
            m0 = fmaxf(m0, lrelu(el4.x + er4.x));
            m1 = fmaxf(m1, lrelu(el4.y + er4.y));
            m2 = fmaxf(m2, lrelu(el4.z + er4.z));
            m3 = fmaxf(m3, lrelu(el4.w + er4.w));
        }
#pragma unroll
        for (int o = 16; o > 0; o >>= 1) {
            m0 = fmaxf(m0, __shfl_xor_sync(0xffffffffu, m0, o));
            m1 = fmaxf(m1, __shfl_xor_sync(0xffffffffu, m1, o));
            m2 = fmaxf(m2, __shfl_xor_sync(0xffffffffu, m2, o));
            m3 = fmaxf(m3, __shfl_xor_sync(0xffffffffu, m3, o));
        }
        // pass B: denom
        float d0 = 0.f, d1 = 0.f, d2 = 0.f, d3 = 0.f;
        for (int i = start + lane; i < end; i += 32) {
            int s = g_esrc[i];
            float4 el4 = *reinterpret_cast<const float4*>(&g_el[s * 4]);
            d0 += __expf(lrelu(el4.x + er4.x) - m0);
            d1 += __expf(lrelu(el4.y + er4.y) - m1);
            d2 += __expf(lrelu(el4.z + er4.z) - m2);
            d3 += __expf(lrelu(el4.w + er4.w) - m3);
        }
#pragma unroll
        for (int o = 16; o > 0; o >>= 1) {
            d0 += __shfl_xor_sync(0xffffffffu, d0, o);
            d1 += __shfl_xor_sync(0xffffffffu, d1, o);
            d2 += __shfl_xor_sync(0xffffffffu, d2, o);
            d3 += __shfl_xor_sync(0xffffffffu, d3, o);
        }
        float i0 = 1.f / fmaxf(d0, 1e-9f);
        float i1 = 1.f / fmaxf(d1, 1e-9f);
        float i2 = 1.f / fmaxf(d2, 1e-9f);
        float i3 = 1.f / fmaxf(d3, 1e-9f);
        // pass C: weighted gather-sum, software-pipelined 1 deep.
        int s_cur = g_esrc[start];
        float4 el_cur = *reinterpret_cast<const float4*>(&g_el[s_cur * 4]);
        for (int i = start; i < end; i++) {
            int s_nxt = 0;
            float4 el_nxt = el_cur;
            if (i + 1 < end) {
                s_nxt = g_esrc[i + 1];
                el_nxt = *reinterpret_cast<const float4*>(&g_el[s_nxt * 4]);
            }
            float a0 = __expf(lrelu(el_cur.x + er4.x) - m0) * i0;
            float a1 = __expf(lrelu(el_cur.y + er4.y) - m1) * i1;
            float a2 = __expf(lrelu(el_cur.z + er4.z) - m2) * i2;
            float a3 = __expf(lrelu(el_cur.w + er4.w) - m3) * i3;
            const float* fr = &feat[(long)s_cur * FD];
#pragma unroll
            for (int k = 0; k < 8; k++) {
                float a = (k < 2) ? a0 : (k < 4) ? a1 : (k < 6) ? a2 : a3;
                acc[k] = fmaf(a, fr[k * 32 + lane], acc[k]);
            }
            s_cur = s_nxt;
            el_cur = el_nxt;
        }
    }
#pragma unroll
    for (int k = 0; k < 8; k++) {
        int f = k * 32 + lane;
        float v = acc[k] + bias[f];
        out[(long)n * FD + f] = v > 0.f ? v : 0.f;
    }
}

// ---------------- pooling ----------------
__global__ void pool_init_kernel() {
    int i = blockIdx.x * blockDim.x + threadIdx.x;
    if (i < NG * HID) g_pool[i] = f2ord(-3.0e38f);
}
__global__ __launch_bounds__(256) void pool_kernel(const int* __restrict__ graph_ids) {
    int n    = blockIdx.x * 8 + (threadIdx.x >> 5);
    int lane = threadIdx.x & 31;
    if (n >= NN) return;
    int g = graph_ids[n];
    const float* x = &g_featB[(long)n * FD];
#pragma unroll
    for (int r = 0; r < 2; r++) {
        int d = lane + r * 32;
        float hm = 0.25f * (x[d] + x[64 + d] + x[128 + d] + x[192 + d]);
        atomicMax(&g_pool[g * HID + d], f2ord(hm));
    }
}
__global__ void classifier_kernel(const float* __restrict__ Wc,
                                  const float* __restrict__ bc,
                                  float* __restrict__ out)
{
    int t = blockIdx.x * blockDim.x + threadIdx.x;
    if (t >= NG * NC) return;
    int g = t / NC;
    int c = t % NC;
    float s = bc[c];
#pragma unroll 8
    for (int d = 0; d < HID; d++)
        s = fmaf(ord2f(g_pool[g * HID + d]), Wc[d * NC + c], s);
    out[t] = s;
}

// ---------------- host launcher ----------------
extern "C" void kernel_launch(void* const* d_in, const int* in_sizes, int n_in,
                              void* d_out, int out_size)
{
    const float* h   = (const float*)d_in[0];
    const float* W1  = (const float*)d_in[1];
    const float* al1 = (const float*)d_in[2];
    const float* ar1 = (const float*)d_in[3];
    const float* b1  = (const float*)d_in[4];
    const float* W2  = (const float*)d_in[5];
    const float* al2 = (const float*)d_in[6];
    const float* ar2 = (const float*)d_in[7];
    const float* b2  = (const float*)d_in[8];
    const float* Wc  = (const float*)d_in[9];
    const float* bc  = (const float*)d_in[10];
    const int* ei    = (const int*)d_in[11];
    const int* gid   = (const int*)d_in[12];
    float* out = (float*)d_out;

    void *pA = nullptr, *pB = nullptr;
    cudaGetSymbolAddress(&pA, g_featA);
    cudaGetSymbolAddress(&pB, g_featB);
    float* featA = (float*)pA;
    float* featB = (float*)pB;

    const int warp_blocks = (NN + 7) / 8;   // 8 warps per 256-thread block
    const int gemm_blocks = (NN + 127) / 128;

    // CSR build (layer-independent)
    zero_cnt_kernel<<<(NN + 255) / 256, 256>>>();
    count_deg_kernel<<<(NE + 255) / 256, 256>>>(ei);
    scan_kernel<<<1, 1024>>>();
    zero_cnt_kernel<<<(NN + 255) / 256, 256>>>();
    scatter_kernel<<<(NE + 255) / 256, 256>>>(ei);

    // Layer 1: fused tf32 GEMM + attention coefficients
    gemm_attn_kernel<IND><<<gemm_blocks, 256>>>(h, W1, featA, al1, ar1);
    gat_aggregate_kernel<<<warp_blocks, 256>>>(featA, b1, featB);

    // Layer 2
    gemm_attn_kernel<FD><<<gemm_blocks, 256>>>(featB, W2, featA, al2, ar2);
    gat_aggregate_kernel<<<warp_blocks, 256>>>(featA, b2, featB);

    // Head-mean + per-graph max pool + classifier
    pool_init_kernel<<<(NG * HID + 255) / 256, 256>>>();
    pool_kernel<<<warp_blocks, 256>>>(gid);
    classifier_kernel<<<(NG * NC + 255) / 256, 256>>>(Wc, bc, out);
}